// round 16
// baseline (speedup 1.0000x reference)
#include <cuda_runtime.h>
#include <cstdint>

#define NBOX 8192
#define M 64
#define D_IN 2376
#define H 1024
#define NCLS 150
#define IOU_T 0.01f
#define G 256

typedef unsigned int u32;
typedef unsigned long long u64;

// -------- persistent device scratch (allocation-free rule) --------
__device__ int   g_sel[M];
__device__ float g_x[M * D_IN];
__device__ float g_h1[M * H];
__device__ float g_h2[M * H];
__device__ float g_part[1048576];    // [slot(sl*CB+cb)][64*64]
__device__ u32   g_bins[4096];       // zero-init; re-zeroed each launch (P5)
__device__ u64   g_cand[2048];
__device__ u64   g_sorted[2048];
__device__ int   g_ccnt;             // candidate counter (re-zeroed each launch)
__device__ float g_sink;
// hierarchical barrier state (all monotonic; reset at exit)
__device__ int   g_sub[8 * 32];      // 8 counters, 128B apart
__device__ int   g_root;
__device__ int   g_epoch;
__device__ int   g_exit;

__device__ __forceinline__ bool iou_gt(float4 k, float ka, float4 c, float ca) {
    float ix1 = fmaxf(k.x, c.x), iy1 = fmaxf(k.y, c.y);
    float ix2 = fminf(k.z, c.z), iy2 = fminf(k.w, c.w);
    float iw = fmaxf(ix2 - ix1, 0.f), ih = fmaxf(iy2 - iy1, 0.f);
    float inter = iw * ih;
    return inter > IOU_T * (ka + ca - inter + 1e-9f);
}

// ---- cp.async helpers ----
__device__ __forceinline__ unsigned smem_u32p(const void* p) {
    return (unsigned)__cvta_generic_to_shared(p);
}
__device__ __forceinline__ void cp16(unsigned dst, const float* src) {
    asm volatile("cp.async.cg.shared.global [%0], [%1], 16;" :: "r"(dst), "l"(src));
}
__device__ __forceinline__ void cp4(unsigned dst, const float* src) {
    asm volatile("cp.async.ca.shared.global [%0], [%1], 4;" :: "r"(dst), "l"(src));
}
#define CP_COMMIT() asm volatile("cp.async.commit_group;" ::: "memory")
#define CP_WAIT2()  asm volatile("cp.async.wait_group 2;" ::: "memory")
#define CP_WAIT0()  asm volatile("cp.async.wait_group 0;" ::: "memory")

// ---- hierarchical grid barrier (phase is 1-based epoch target) ----
__device__ __forceinline__ void gsync(int phase, int tid, int vb) {
    __threadfence();
    __syncthreads();
    if (tid == 0) {
        const int grp = vb & 7;
        int old = atomicAdd(&g_sub[grp * 32], 1);
        if (old == phase * 32 - 1) {                 // last of this group, this phase
            int r = atomicAdd(&g_root, 1);
            if (r == phase * 8 - 1) {                // last group overall
                atomicExch(&g_epoch, phase);         // release the grid
            }
        }
        while (*(volatile int*)&g_epoch < phase) __nanosleep(32);
    }
    __syncthreads();
    __threadfence();
}

// ---- L2 weight prefetch stripe ----
__device__ __forceinline__ void prefetch_stripe(const float* w, int n4,
                                                int blk, int nblk, int tid) {
    const float4* p = (const float4*)w;
    int per = (n4 + nblk - 1) / nblk;
    int s0 = blk * per;
    int s1 = min(s0 + per, n4);
    float acc = 0.f;
    for (int i = s0 + tid; i < s1; i += 256) acc += __ldcg(&p[i]).x;
    if (__float_as_uint(acc) == 0x7f800001u) g_sink = acc;   // never true
}

// ============================================================
// GEMM phase: 64x64 col-tile x K-slice, 4-stage cp.async pipeline
// ============================================================
template<int FULLN>
__device__ void gemm_phase(const float* __restrict__ A, int lda,
                           const float* __restrict__ Wm, int N,
                           int cb, int sl, int kps, int K, int CB, int tid,
                           float (*As)[64][20], float (*Ws)[16][68])
{
    const int row0 = (tid >> 4) * 4;
    const int cl   = (tid & 15) * 4;
    const int k0 = sl * kps;
    const int k1 = min(k0 + kps, K);

    if (!FULLN) {
        for (int t = tid; t < 4 * 16 * 68; t += 256) (&Ws[0][0][0])[t] = 0.f;
        __syncthreads();
    }

    float acc[4][4] = {};

    auto stageA = [&](int buf, int kb) {
        const int r = tid >> 2;
        const int kk4 = (tid & 3) * 4;
        const int j = kb + kk4;
        if (j < k1)
            cp16(smem_u32p(&As[buf][r][kk4]), A + (size_t)r * lda + j);
    };
    auto stageW = [&](int buf, int kb) {
        if (FULLN) {
            const int kk = tid >> 4;
            const int n4 = (tid & 15) * 4;
            const int j = kb + kk;
            if (j < k1)
                cp16(smem_u32p(&Ws[buf][kk][n4]), Wm + (size_t)j * N + cb * 64 + n4);
        } else {
            #pragma unroll
            for (int i = 0; i < 4; ++i) {
                int idx = tid + 256 * i;
                int kk = idx >> 6, c = idx & 63;
                int j = kb + kk, col = cb * 64 + c;
                if (j < k1 && col < N)
                    cp4(smem_u32p(&Ws[buf][kk][c]), Wm + (size_t)j * N + col);
            }
        }
    };

    const int nChunk = (k1 - k0 + 15) >> 4;
    #pragma unroll
    for (int s = 0; s < 3; ++s) {
        if (s < nChunk) { stageA(s, k0 + s * 16); stageW(s, k0 + s * 16); }
        CP_COMMIT();
    }

    for (int c = 0; c < nChunk; ++c) {
        CP_WAIT2();
        __syncthreads();
        {
            const int s = c + 3;
            if (s < nChunk) { stageA(s & 3, k0 + s * 16); stageW(s & 3, k0 + s * 16); }
            CP_COMMIT();
        }
        const int kbn = min(16, k1 - (k0 + c * 16));
        const float (*Ab)[20] = As[c & 3];
        const float (*Wb)[68] = Ws[c & 3];

        #define KK_BODY(kk)                                                    \
        {                                                                      \
            float a0 = Ab[row0 + 0][kk], a1 = Ab[row0 + 1][kk];                \
            float a2 = Ab[row0 + 2][kk], a3 = Ab[row0 + 3][kk];                \
            float4 w = *reinterpret_cast<const float4*>(&Wb[kk][cl]);          \
            acc[0][0] += a0 * w.x; acc[0][1] += a0 * w.y;                      \
            acc[0][2] += a0 * w.z; acc[0][3] += a0 * w.w;                      \
            acc[1][0] += a1 * w.x; acc[1][1] += a1 * w.y;                      \
            acc[1][2] += a1 * w.z; acc[1][3] += a1 * w.w;                      \
            acc[2][0] += a2 * w.x; acc[2][1] += a2 * w.y;                      \
            acc[2][2] += a2 * w.z; acc[2][3] += a2 * w.w;                      \
            acc[3][0] += a3 * w.x; acc[3][1] += a3 * w.y;                      \
            acc[3][2] += a3 * w.z; acc[3][3] += a3 * w.w;                      \
        }
        if (kbn == 16) {
            #pragma unroll
            for (int kk = 0; kk < 16; ++kk) KK_BODY(kk)
        } else {
            #pragma unroll 8
            for (int kk = 0; kk < kbn; ++kk) KK_BODY(kk)
        }
        #undef KK_BODY
    }

    CP_WAIT0();
    __syncthreads();

    float* p = g_part + (size_t)(sl * CB + cb) * 4096;
    #pragma unroll
    for (int r = 0; r < 4; ++r)
        *reinterpret_cast<float4*>(&p[(row0 + r) * 64 + cl]) =
            make_float4(acc[r][0], acc[r][1], acc[r][2], acc[r][3]);
}

// 1024-col layer reduce
__device__ __forceinline__ void reduce_h(
    const float* __restrict__ bias, const float* __restrict__ bn,
    float* __restrict__ out, int vb, int tid)
{
    int idx = vb * 256 + tid;
    int r = idx >> 10, col = idx & 1023;
    int cb = col >> 6, c = col & 63;
    float s = 0.f;
    #pragma unroll
    for (int si = 0; si < 16; ++si)
        s += __ldcg(&g_part[(size_t)(si * 16 + cb) * 4096 + r * 64 + c]);
    s += bias[col];
    s = (s - bn[2048 + col]) * rsqrtf(bn[3072 + col] + 1e-5f) * bn[col] + bn[1024 + col];
    out[r * 1024 + col] = fmaxf(s, 0.f);
}

// ============================================================
// THE fused persistent kernel, grid=256, 12 grid barriers.
// ============================================================
__global__ void __launch_bounds__(256, 2) fused_kernel(
    const float* __restrict__ boxes, const float* __restrict__ scores,
    const int* __restrict__ labels, const float* __restrict__ features,
    const float* __restrict__ embed_w, const float* __restrict__ bn_pos,
    const float* __restrict__ pos_w, const float* __restrict__ pos_b,
    const float* __restrict__ lin1_w, const float* __restrict__ lin1_b,
    const float* __restrict__ bn1,
    const float* __restrict__ lin2_w, const float* __restrict__ lin2_b,
    const float* __restrict__ bn2,
    const float* __restrict__ lin3_w, const float* __restrict__ lin3_b,
    const float* __restrict__ bn3,
    const float* __restrict__ lin4_w, const float* __restrict__ lin4_b,
    float* __restrict__ d_out, int out_size)
{
    __shared__ __align__(16) unsigned char smraw[38912];
    __shared__ u32 s_ws[16];
    const int tid = threadIdx.x, vb = blockIdx.x;
    const int lane = tid & 31, wrp = tid >> 5;
    const unsigned FULL = 0xffffffffu;
    const float4* boxes4 = (const float4*)boxes;
    int ph = 1;

    // ---------- P1: histogram (blocks 0..31) / prefetch lin1 ----------
    {
        int gt = vb * 256 + tid;
        if (gt < NBOX) {
            u32 b = __float_as_uint(scores[gt]);
            u32 f = b ^ ((b >> 31) ? 0xFFFFFFFFu : 0x80000000u);
            atomicAdd(&g_bins[(~f) >> 20], 1u);
        } else {
            prefetch_stripe(lin1_w, (D_IN * H) / 4, vb - 32, G - 32, tid);
        }
    }
    gsync(ph, tid, vb); ph++;

    // ---------- P2: local threshold scan + compaction (blocks 0..31) ----------
    u32 B = 0; int NSEL = 0;
    if (vb < 32) {
        int t16 = tid * 16;
        u32 v[16]; u32 s = 0;
        #pragma unroll
        for (int i = 0; i < 16; ++i) { v[i] = __ldcg(&g_bins[t16 + i]); s += v[i]; }
        u32 x = s;
        #pragma unroll
        for (int o = 1; o < 32; o <<= 1) {
            u32 y = __shfl_up_sync(FULL, x, o);
            if (lane >= o) x += y;
        }
        if (lane == 31) s_ws[wrp] = x;
        __syncthreads();
        if (wrp == 0 && lane < 8) {
            u32 vv = s_ws[lane], xx = vv;
            #pragma unroll
            for (int o = 1; o < 8; o <<= 1) {
                u32 y = __shfl_up_sync(0xffu, xx, o);
                if (lane >= o) xx += y;
            }
            s_ws[lane] = xx - vv;
        }
        __syncthreads();
        u32 run = s_ws[wrp] + (x - s);
        int* stt = (int*)smraw;      // [0]=Braw [1]=cumIncl [2]=cumExcl
        #pragma unroll
        for (int i = 0; i < 16; ++i) {
            if (run < 512 && run + v[i] >= 512) {
                stt[0] = t16 + i;
                stt[1] = (int)(run + v[i]);
                stt[2] = (int)run;
            }
            run += v[i];
        }
        __syncthreads();
        int Braw = stt[0], cumI = stt[1], cumE = stt[2];
        if (cumI <= 2048) { B = (u32)Braw;     NSEL = cumI; }
        else              { B = (u32)Braw - 1; NSEL = cumE; }
        __syncthreads();

        // compaction
        int gt = vb * 256 + tid;
        u32 b = __float_as_uint(scores[gt]);
        u32 f = b ^ ((b >> 31) ? 0xFFFFFFFFu : 0x80000000u);
        u32 k = ~f;
        if ((k >> 20) <= B) {
            int pos = atomicAdd(&g_ccnt, 1);
            if (pos < 2048) g_cand[pos] = ((u64)k << 32) | (u32)gt;
        }
    } else {
        prefetch_stripe(lin2_w, (H * H) / 4, vb - 32, G - 32, tid);
    }
    gsync(ph, tid, vb); ph++;

    // ---------- P3: parallel rank-sort (selecting blocks) / prefetch lin3+lin4 ----------
    if (vb < 32 && vb * 256 < NSEL) {
        u64* cand = (u64*)smraw;
        for (int t = tid; t < NSEL; t += 256) cand[t] = __ldcg(&g_cand[t]);
        __syncthreads();
        int c = vb * 256 + tid;
        if (c < NSEL) {
            u64 mine = cand[c];
            int r = 0;
            for (int j = 0; j < NSEL; ++j) r += (cand[j] < mine);
            g_sorted[r] = mine;
        }
    } else if (vb >= 32 && vb < 208) {
        prefetch_stripe(lin3_w, (H * H) / 4, vb - 32, 176, tid);
    } else if (vb >= 208) {
        prefetch_stripe(lin4_w, (H * NCLS) / 4, vb - 208, 48, tid);
    }
    gsync(ph, tid, vb); ph++;

    // ---------- P4: NMS + outputs (block 0 only) ----------
    if (vb == 0) {
        float4* cbx      = (float4*)smraw;            // 8KB
        int*    cord     = (int*)(smraw + 8192);      // 2KB
        float4* keptBox  = (float4*)(smraw + 10240);  // 1KB
        float*  keptArea = (float*)(smraw + 11264);
        int*    s_sel    = (int*)(smraw + 11520);
        int*    s_supp   = (int*)(smraw + 11776);
        int*    st       = (int*)(smraw + 12032);

        const int NC = NSEL < 512 ? NSEL : 512;
        for (int t = tid; t < NC; t += 256) {
            u64 e = __ldcg(&g_sorted[t]);
            int oi = (int)(u32)(e & 0xffffffffu);
            cord[t] = oi;
            cbx[t] = boxes4[oi];
        }
        if (tid == 0) { st[0] = 0; st[1] = 0; }
        __syncthreads();

        if (tid < 32) {
            int kept = 0, supp = 0;
            for (int c0 = 0; c0 < NC && kept < 64; c0 += 32) {
                const int cEnd = min(32, NC - c0);
                const bool valid = (lane < cEnd);
                float4 mb = valid ? cbx[c0 + lane] : make_float4(0, 0, 0, 0);
                float ma = (mb.z - mb.x) * (mb.w - mb.y);

                bool supK = false;
                for (int k = 0; k < kept; ++k)
                    supK |= iou_gt(keptBox[k], keptArea[k], mb, ma);

                u32 col = 0;
                for (int i = 0; i < cEnd; ++i) {
                    float4 bi = cbx[c0 + i];
                    float ai = (bi.z - bi.x) * (bi.w - bi.y);
                    bool s = (i < lane) && valid && iou_gt(bi, ai, mb, ma);
                    col |= (u32)s << i;
                }

                bool alive = valid && !supK;
                for (int i = 0; i < cEnd; ++i) {
                    u32 bal = __ballot_sync(FULL, alive);
                    if (bal & (1u << i)) {
                        if (lane == i) { keptBox[kept] = mb; keptArea[kept] = ma; }
                        if (lane == 0) s_sel[kept] = cord[c0 + i];
                        if (col & (1u << i)) alive = false;
                        kept++;
                        if (kept == 64) break;
                    } else {
                        if (lane == 0 && supp < 64) s_supp[supp] = cord[c0 + i];
                        supp++;
                    }
                }
                __syncwarp();
            }
            if (lane == 0) { st[0] = kept; st[1] = supp > 64 ? 64 : supp; }
        }
        __syncthreads();

        // fallback: continue serial NMS past NC (rare)
        if (st[0] < 64 && NC < NSEL) {
            float4 kb0 = make_float4(0, 0, 0, 0), kb1 = make_float4(0, 0, 0, 0);
            float ka0 = 0.f, ka1 = 0.f;
            int kept = st[0], supp = st[1];
            if (tid < 32) {
                if (tid < kept)      { kb0 = keptBox[tid];      ka0 = keptArea[tid]; }
                if (tid + 32 < kept) { kb1 = keptBox[tid + 32]; ka1 = keptArea[tid + 32]; }
            }
            __syncthreads();
            for (int c0 = NC; c0 < NSEL; c0 += 512) {
                const int cnt = min(512, NSEL - c0);
                for (int t = tid; t < cnt; t += 256) {
                    u64 e = __ldcg(&g_sorted[c0 + t]);
                    int oi = (int)(u32)(e & 0xffffffffu);
                    cord[t] = oi;
                    cbx[t] = boxes4[oi];
                }
                __syncthreads();
                if (tid < 32) {
                    #pragma unroll 1
                    for (int ii = 0; ii < cnt; ++ii) {
                        float4 c = cbx[ii];
                        float ca = (c.z - c.x) * (c.w - c.y);
                        bool sup = false;
                        if (tid < kept)      sup  = iou_gt(kb0, ka0, c, ca);
                        if (tid + 32 < kept) sup |= iou_gt(kb1, ka1, c, ca);
                        unsigned m = __ballot_sync(FULL, sup);
                        if (m == 0) {
                            int slot = kept;
                            if (slot < 32) { if (tid == slot)      { kb0 = c; ka0 = ca; } }
                            else           { if (tid == slot - 32) { kb1 = c; ka1 = ca; } }
                            if (tid == 0) s_sel[slot] = cord[ii];
                            kept++;
                            if (kept == 64) break;
                        } else if (supp < 64) {
                            if (tid == 0) s_supp[supp] = cord[ii];
                            supp++;
                        }
                    }
                    if (tid == 0) { st[0] = kept; st[1] = supp; }
                }
                __syncthreads();
                if (st[0] >= 64) break;
                __syncthreads();
            }
        }
        __syncthreads();

        const int keptF = st[0];
        if (tid < 64) {
            int oi = (tid < keptF) ? s_sel[tid] : s_supp[tid - keptF];
            g_sel[tid] = oi;
            if (9600 + tid < out_size) d_out[9600 + tid] = (float)labels[oi];
            if (9664 + tid < out_size) d_out[9664 + tid] = scores[oi];
        }
    }
    gsync(ph, tid, vb); ph++;

    // ---------- P5: gather + x-tails + scratch re-zero (whole grid) ----------
    {
        int gt = vb * 256 + tid;
        if (vb < 128) {
            int r = gt >> 9, c = gt & 511;
            int oi = __ldcg(&g_sel[r]);
            ((float4*)(g_x + r * D_IN))[c] =
                ((const float4*)(features + (size_t)oi * 2048))[c];
        } else if (vb < 192) {
            int e = gt - 128 * 256;
            if (e < 12800) {
                int r = e / 200, c = e - r * 200;
                int lab = labels[__ldcg(&g_sel[r])] - 1;
                g_x[r * D_IN + 2048 + c] = embed_w[lab * 200 + c];
            }
        } else if (vb < 224) {
            int p = gt - 192 * 256;
            int r = p >> 7, c = p & 127;
            int oi = __ldcg(&g_sel[r]);
            float x1 = boxes[oi * 4 + 0], y1 = boxes[oi * 4 + 1];
            float x2 = boxes[oi * 4 + 2], y2 = boxes[oi * 4 + 3];
            float w = x2 - x1 + 1.f, h = y2 - y1 + 1.f;
            float cs[4] = { x1 + 0.5f * w, y1 + 0.5f * h, w, h };
            float acc = pos_b[c];
            #pragma unroll
            for (int i = 0; i < 4; ++i) {
                float v = (cs[i] - bn_pos[8 + i]) * rsqrtf(bn_pos[12 + i] + 1e-5f)
                          * bn_pos[i] + bn_pos[4 + i];
                acc += v * pos_w[i * 128 + c];
            }
            g_x[r * D_IN + 2248 + c] = fmaxf(acc, 0.f);
        } else {
            int z = gt - 224 * 256;
            if (z < 4096) g_bins[z] = 0;
            if (z == 4096) g_ccnt = 0;
        }
    }
    gsync(ph, tid, vb); ph++;

    // ---------- MLP chain ----------
    float (*As)[64][20] = (float(*)[64][20])smraw;
    float (*Ws)[16][68] = (float(*)[16][68])(smraw + 20480);

    gemm_phase<1>(g_x, D_IN, lin1_w, H, vb & 15, vb >> 4, 152, D_IN, 16, tid, As, Ws);
    gsync(ph, tid, vb); ph++;
    reduce_h(lin1_b, bn1, g_h1, vb, tid);
    gsync(ph, tid, vb); ph++;

    gemm_phase<1>(g_h1, H, lin2_w, H, vb & 15, vb >> 4, 64, H, 16, tid, As, Ws);
    gsync(ph, tid, vb); ph++;
    reduce_h(lin2_b, bn2, g_h2, vb, tid);
    gsync(ph, tid, vb); ph++;

    gemm_phase<1>(g_h2, H, lin3_w, H, vb & 15, vb >> 4, 64, H, 16, tid, As, Ws);
    gsync(ph, tid, vb); ph++;
    reduce_h(lin3_b, bn3, g_h1, vb, tid);
    gsync(ph, tid, vb); ph++;

    if (vb < 48)
        gemm_phase<0>(g_h1, H, lin4_w, NCLS, vb % 3, vb / 3, 64, H, 3, tid, As, Ws);
    gsync(ph, tid, vb); ph++;

    {
        int idx = vb * 256 + tid;
        if (idx < 9600) {
            int r = idx / 150, col = idx - r * 150;
            int cb = col >> 6, c = col & 63;
            float s = 0.f;
            #pragma unroll
            for (int si = 0; si < 16; ++si)
                s += __ldcg(&g_part[(size_t)(si * 3 + cb) * 4096 + r * 64 + c]);
            d_out[idx] = s + lin4_b[col];
        }
    }

    // exit: last block resets barrier state for next launch / replay
    __syncthreads();
    if (tid == 0) {
        __threadfence();
        int old = atomicAdd(&g_exit, 1);
        if (old == G - 1) {
            #pragma unroll
            for (int i = 0; i < 8; ++i) g_sub[i * 32] = 0;
            g_root = 0;
            g_epoch = 0;
            g_exit = 0;
            __threadfence();
        }
    }
}

// ============================================================
extern "C" void kernel_launch(void* const* d_in, const int* in_sizes, int n_in,
                              void* d_out_v, int out_size)
{
    const float* boxes    = (const float*)d_in[0];
    const float* scores   = (const float*)d_in[1];
    const int*   labels   = (const int*)  d_in[2];
    const float* features = (const float*)d_in[3];
    const float* embed_w  = (const float*)d_in[4];
    const float* bn_pos   = (const float*)d_in[5];
    const float* pos_w    = (const float*)d_in[6];
    const float* pos_b    = (const float*)d_in[7];
    const float* lin1_w   = (const float*)d_in[8];
    const float* lin1_b   = (const float*)d_in[9];
    const float* bn1      = (const float*)d_in[10];
    const float* lin2_w   = (const float*)d_in[11];
    const float* lin2_b   = (const float*)d_in[12];
    const float* bn2      = (const float*)d_in[13];
    const float* lin3_w   = (const float*)d_in[14];
    const float* lin3_b   = (const float*)d_in[15];
    const float* bn3      = (const float*)d_in[16];
    const float* lin4_w   = (const float*)d_in[17];
    const float* lin4_b   = (const float*)d_in[18];
    float* d_out = (float*)d_out_v;

    fused_kernel<<<G, 256>>>(boxes, scores, labels, features, embed_w,
                             bn_pos, pos_w, pos_b,
                             lin1_w, lin1_b, bn1,
                             lin2_w, lin2_b, bn2,
                             lin3_w, lin3_b, bn3,
                             lin4_w, lin4_b, d_out, out_size);
}

// round 17
// speedup vs baseline: 1.0598x; 1.0598x over previous
#include <cuda_runtime.h>
#include <cstdint>

#define NBOX 8192
#define M 64
#define D_IN 2376
#define H 1024
#define NCLS 150
#define IOU_T 0.01f
#define G 256

typedef unsigned int u32;
typedef unsigned long long u64;

// -------- persistent device scratch (allocation-free rule) --------
__device__ int   g_sel[M];
__device__ float g_x[M * D_IN];
__device__ float g_h1[M * H];
__device__ float g_h2[M * H];
__device__ float g_part[1048576];    // [slot(sl*CB+cb)][64*64]
__device__ u32   g_bins[4096];       // zero-init; re-zeroed mid-kernel each launch
__device__ u64   g_cand[2048];
__device__ u64   g_sorted[2048];
__device__ int   g_ccnt;             // candidate counter (re-zeroed each launch)
__device__ float g_sink;
// sync state (all monotonic; reset at exit)
__device__ int   g_selbar;           // 32-block sub-barrier counter
__device__ int   g_nmsdone;          // flag: g_sel/outputs ready
__device__ int   g_gcnt;             // gather-completion counter (to 32)
__device__ int   g_xready;           // flag: g_x fully built
__device__ int   g_bar;              // full-grid barrier counter
__device__ int   g_exit;

__device__ __forceinline__ bool iou_gt(float4 k, float ka, float4 c, float ca) {
    float ix1 = fmaxf(k.x, c.x), iy1 = fmaxf(k.y, c.y);
    float ix2 = fminf(k.z, c.z), iy2 = fminf(k.w, c.w);
    float iw = fmaxf(ix2 - ix1, 0.f), ih = fmaxf(iy2 - iy1, 0.f);
    float inter = iw * ih;
    return inter > IOU_T * (ka + ca - inter + 1e-9f);
}

// ---- cp.async helpers ----
__device__ __forceinline__ unsigned smem_u32p(const void* p) {
    return (unsigned)__cvta_generic_to_shared(p);
}
__device__ __forceinline__ void cp16(unsigned dst, const float* src) {
    asm volatile("cp.async.cg.shared.global [%0], [%1], 16;" :: "r"(dst), "l"(src));
}
__device__ __forceinline__ void cp4(unsigned dst, const float* src) {
    asm volatile("cp.async.ca.shared.global [%0], [%1], 4;" :: "r"(dst), "l"(src));
}
#define CP_COMMIT() asm volatile("cp.async.commit_group;" ::: "memory")
#define CP_WAIT2()  asm volatile("cp.async.wait_group 2;" ::: "memory")
#define CP_WAIT0()  asm volatile("cp.async.wait_group 0;" ::: "memory")

// ---- full-grid flat barrier (measured-good R15 pattern) ----
__device__ __forceinline__ void gsync(int target, int tid) {
    __threadfence();
    __syncthreads();
    if (tid == 0) {
        atomicAdd(&g_bar, 1);
        while (*(volatile int*)&g_bar < target) __nanosleep(64);
    }
    __syncthreads();
    __threadfence();
}

// ---- 32-block sub-barrier for the selection team ----
__device__ __forceinline__ void subsync(int phase, int tid) {
    __threadfence();
    __syncthreads();
    if (tid == 0) {
        atomicAdd(&g_selbar, 1);
        while (*(volatile int*)&g_selbar < phase * 32) __nanosleep(32);
    }
    __syncthreads();
    __threadfence();
}

// ---- one-way flag wait ----
__device__ __forceinline__ void flagwait(volatile int* f, int tid) {
    __syncthreads();
    if (tid == 0) { while (*f == 0) __nanosleep(64); }
    __syncthreads();
    __threadfence();
}

// ---- L2 weight prefetch stripe ----
__device__ __forceinline__ void prefetch_stripe(const float* w, int n4,
                                                int blk, int nblk, int tid) {
    const float4* p = (const float4*)w;
    int per = (n4 + nblk - 1) / nblk;
    int s0 = blk * per;
    int s1 = min(s0 + per, n4);
    float acc = 0.f;
    for (int i = s0 + tid; i < s1; i += 256) acc += __ldcg(&p[i]).x;
    if (__float_as_uint(acc) == 0x7f800001u) g_sink = acc;   // never true
}

// ============================================================
// GEMM phase: 64x64 col-tile x K-slice, 4-stage cp.async pipeline
// ============================================================
template<int FULLN>
__device__ void gemm_phase(const float* __restrict__ A, int lda,
                           const float* __restrict__ Wm, int N,
                           int cb, int sl, int kps, int K, int CB, int tid,
                           float (*As)[64][20], float (*Ws)[16][68])
{
    const int row0 = (tid >> 4) * 4;
    const int cl   = (tid & 15) * 4;
    const int k0 = sl * kps;
    const int k1 = min(k0 + kps, K);

    if (!FULLN) {
        for (int t = tid; t < 4 * 16 * 68; t += 256) (&Ws[0][0][0])[t] = 0.f;
        __syncthreads();
    }

    float acc[4][4] = {};

    auto stageA = [&](int buf, int kb) {
        const int r = tid >> 2;
        const int kk4 = (tid & 3) * 4;
        const int j = kb + kk4;
        if (j < k1)
            cp16(smem_u32p(&As[buf][r][kk4]), A + (size_t)r * lda + j);
    };
    auto stageW = [&](int buf, int kb) {
        if (FULLN) {
            const int kk = tid >> 4;
            const int n4 = (tid & 15) * 4;
            const int j = kb + kk;
            if (j < k1)
                cp16(smem_u32p(&Ws[buf][kk][n4]), Wm + (size_t)j * N + cb * 64 + n4);
        } else {
            #pragma unroll
            for (int i = 0; i < 4; ++i) {
                int idx = tid + 256 * i;
                int kk = idx >> 6, c = idx & 63;
                int j = kb + kk, col = cb * 64 + c;
                if (j < k1 && col < N)
                    cp4(smem_u32p(&Ws[buf][kk][c]), Wm + (size_t)j * N + col);
            }
        }
    };

    const int nChunk = (k1 - k0 + 15) >> 4;
    #pragma unroll
    for (int s = 0; s < 3; ++s) {
        if (s < nChunk) { stageA(s, k0 + s * 16); stageW(s, k0 + s * 16); }
        CP_COMMIT();
    }

    for (int c = 0; c < nChunk; ++c) {
        CP_WAIT2();
        __syncthreads();
        {
            const int s = c + 3;
            if (s < nChunk) { stageA(s & 3, k0 + s * 16); stageW(s & 3, k0 + s * 16); }
            CP_COMMIT();
        }
        const int kbn = min(16, k1 - (k0 + c * 16));
        const float (*Ab)[20] = As[c & 3];
        const float (*Wb)[68] = Ws[c & 3];

        #define KK_BODY(kk)                                                    \
        {                                                                      \
            float a0 = Ab[row0 + 0][kk], a1 = Ab[row0 + 1][kk];                \
            float a2 = Ab[row0 + 2][kk], a3 = Ab[row0 + 3][kk];                \
            float4 w = *reinterpret_cast<const float4*>(&Wb[kk][cl]);          \
            acc[0][0] += a0 * w.x; acc[0][1] += a0 * w.y;                      \
            acc[0][2] += a0 * w.z; acc[0][3] += a0 * w.w;                      \
            acc[1][0] += a1 * w.x; acc[1][1] += a1 * w.y;                      \
            acc[1][2] += a1 * w.z; acc[1][3] += a1 * w.w;                      \
            acc[2][0] += a2 * w.x; acc[2][1] += a2 * w.y;                      \
            acc[2][2] += a2 * w.z; acc[2][3] += a2 * w.w;                      \
            acc[3][0] += a3 * w.x; acc[3][1] += a3 * w.y;                      \
            acc[3][2] += a3 * w.z; acc[3][3] += a3 * w.w;                      \
        }
        if (kbn == 16) {
            #pragma unroll
            for (int kk = 0; kk < 16; ++kk) KK_BODY(kk)
        } else {
            #pragma unroll 8
            for (int kk = 0; kk < kbn; ++kk) KK_BODY(kk)
        }
        #undef KK_BODY
    }

    CP_WAIT0();
    __syncthreads();

    float* p = g_part + (size_t)(sl * CB + cb) * 4096;
    #pragma unroll
    for (int r = 0; r < 4; ++r)
        *reinterpret_cast<float4*>(&p[(row0 + r) * 64 + cl]) =
            make_float4(acc[r][0], acc[r][1], acc[r][2], acc[r][3]);
}

// 1024-col layer reduce
__device__ __forceinline__ void reduce_h(
    const float* __restrict__ bias, const float* __restrict__ bn,
    float* __restrict__ out, int vb, int tid)
{
    int idx = vb * 256 + tid;
    int r = idx >> 10, col = idx & 1023;
    int cb = col >> 6, c = col & 63;
    float s = 0.f;
    #pragma unroll
    for (int si = 0; si < 16; ++si)
        s += __ldcg(&g_part[(size_t)(si * 16 + cb) * 4096 + r * 64 + c]);
    s += bias[col];
    s = (s - bn[2048 + col]) * rsqrtf(bn[3072 + col] + 1e-5f) * bn[col] + bn[1024 + col];
    out[r * 1024 + col] = fmaxf(s, 0.f);
}

// ============================================================
// THE fused persistent kernel, grid=256.
// Blocks 0..31: selection pipeline (sub-barriers + flags).
// Blocks 32..255: prefetch weights, park on flags.
// All: MLP chain with 7 full-grid barriers.
// ============================================================
__global__ void __launch_bounds__(256, 2) fused_kernel(
    const float* __restrict__ boxes, const float* __restrict__ scores,
    const int* __restrict__ labels, const float* __restrict__ features,
    const float* __restrict__ embed_w, const float* __restrict__ bn_pos,
    const float* __restrict__ pos_w, const float* __restrict__ pos_b,
    const float* __restrict__ lin1_w, const float* __restrict__ lin1_b,
    const float* __restrict__ bn1,
    const float* __restrict__ lin2_w, const float* __restrict__ lin2_b,
    const float* __restrict__ bn2,
    const float* __restrict__ lin3_w, const float* __restrict__ lin3_b,
    const float* __restrict__ bn3,
    const float* __restrict__ lin4_w, const float* __restrict__ lin4_b,
    float* __restrict__ d_out, int out_size)
{
    __shared__ __align__(16) unsigned char smraw[38912];
    __shared__ u32 s_ws[16];
    const int tid = threadIdx.x, vb = blockIdx.x;
    const int lane = tid & 31, wrp = tid >> 5;
    const unsigned FULL = 0xffffffffu;
    const float4* boxes4 = (const float4*)boxes;

    if (vb < 32) {
        // ===================== SELECTION TEAM =====================
        // S1: histogram (32 blocks x 256 threads cover all 8192)
        {
            int gt = vb * 256 + tid;
            u32 b = __float_as_uint(scores[gt]);
            u32 f = b ^ ((b >> 31) ? 0xFFFFFFFFu : 0x80000000u);
            atomicAdd(&g_bins[(~f) >> 20], 1u);
        }
        subsync(1, tid);

        // S2: local threshold scan + compaction
        u32 B = 0; int NSEL = 0;
        {
            int t16 = tid * 16;
            u32 v[16]; u32 s = 0;
            #pragma unroll
            for (int i = 0; i < 16; ++i) { v[i] = __ldcg(&g_bins[t16 + i]); s += v[i]; }
            u32 x = s;
            #pragma unroll
            for (int o = 1; o < 32; o <<= 1) {
                u32 y = __shfl_up_sync(FULL, x, o);
                if (lane >= o) x += y;
            }
            if (lane == 31) s_ws[wrp] = x;
            __syncthreads();
            if (wrp == 0 && lane < 8) {
                u32 vv = s_ws[lane], xx = vv;
                #pragma unroll
                for (int o = 1; o < 8; o <<= 1) {
                    u32 y = __shfl_up_sync(0xffu, xx, o);
                    if (lane >= o) xx += y;
                }
                s_ws[lane] = xx - vv;
            }
            __syncthreads();
            u32 run = s_ws[wrp] + (x - s);
            int* stt = (int*)smraw;
            #pragma unroll
            for (int i = 0; i < 16; ++i) {
                if (run < 512 && run + v[i] >= 512) {
                    stt[0] = t16 + i;
                    stt[1] = (int)(run + v[i]);
                    stt[2] = (int)run;
                }
                run += v[i];
            }
            __syncthreads();
            int Braw = stt[0], cumI = stt[1], cumE = stt[2];
            if (cumI <= 2048) { B = (u32)Braw;     NSEL = cumI; }
            else              { B = (u32)Braw - 1; NSEL = cumE; }
            __syncthreads();

            int gt = vb * 256 + tid;
            u32 b = __float_as_uint(scores[gt]);
            u32 f = b ^ ((b >> 31) ? 0xFFFFFFFFu : 0x80000000u);
            u32 k = ~f;
            if ((k >> 20) <= B) {
                int pos = atomicAdd(&g_ccnt, 1);
                if (pos < 2048) g_cand[pos] = ((u64)k << 32) | (u32)gt;
            }
        }
        subsync(2, tid);

        // S3: parallel rank-sort (blocks owning candidate ranks)
        if (vb * 256 < NSEL) {
            u64* cand = (u64*)smraw;
            for (int t = tid; t < NSEL; t += 256) cand[t] = __ldcg(&g_cand[t]);
            __syncthreads();
            int c = vb * 256 + tid;
            if (c < NSEL) {
                u64 mine = cand[c];
                int r = 0;
                for (int j = 0; j < NSEL; ++j) r += (cand[j] < mine);
                g_sorted[r] = mine;
            }
        }
        subsync(3, tid);

        // S4: NMS + outputs (block 0 only), then raise g_nmsdone
        if (vb == 0) {
            float4* cbx      = (float4*)smraw;
            int*    cord     = (int*)(smraw + 8192);
            float4* keptBox  = (float4*)(smraw + 10240);
            float*  keptArea = (float*)(smraw + 11264);
            int*    s_sel    = (int*)(smraw + 11520);
            int*    s_supp   = (int*)(smraw + 11776);
            int*    st       = (int*)(smraw + 12032);

            const int NC = NSEL < 512 ? NSEL : 512;
            for (int t = tid; t < NC; t += 256) {
                u64 e = __ldcg(&g_sorted[t]);
                int oi = (int)(u32)(e & 0xffffffffu);
                cord[t] = oi;
                cbx[t] = boxes4[oi];
            }
            if (tid == 0) { st[0] = 0; st[1] = 0; }
            __syncthreads();

            if (tid < 32) {
                int kept = 0, supp = 0;
                for (int c0 = 0; c0 < NC && kept < 64; c0 += 32) {
                    const int cEnd = min(32, NC - c0);
                    const bool valid = (lane < cEnd);
                    float4 mb = valid ? cbx[c0 + lane] : make_float4(0, 0, 0, 0);
                    float ma = (mb.z - mb.x) * (mb.w - mb.y);

                    bool supK = false;
                    for (int k = 0; k < kept; ++k)
                        supK |= iou_gt(keptBox[k], keptArea[k], mb, ma);

                    u32 col = 0;
                    for (int i = 0; i < cEnd; ++i) {
                        float4 bi = cbx[c0 + i];
                        float ai = (bi.z - bi.x) * (bi.w - bi.y);
                        bool s = (i < lane) && valid && iou_gt(bi, ai, mb, ma);
                        col |= (u32)s << i;
                    }

                    bool alive = valid && !supK;
                    for (int i = 0; i < cEnd; ++i) {
                        u32 bal = __ballot_sync(FULL, alive);
                        if (bal & (1u << i)) {
                            if (lane == i) { keptBox[kept] = mb; keptArea[kept] = ma; }
                            if (lane == 0) s_sel[kept] = cord[c0 + i];
                            if (col & (1u << i)) alive = false;
                            kept++;
                            if (kept == 64) break;
                        } else {
                            if (lane == 0 && supp < 64) s_supp[supp] = cord[c0 + i];
                            supp++;
                        }
                    }
                    __syncwarp();
                }
                if (lane == 0) { st[0] = kept; st[1] = supp > 64 ? 64 : supp; }
            }
            __syncthreads();

            // fallback: continue serial NMS past NC (rare)
            if (st[0] < 64 && NC < NSEL) {
                float4 kb0 = make_float4(0, 0, 0, 0), kb1 = make_float4(0, 0, 0, 0);
                float ka0 = 0.f, ka1 = 0.f;
                int kept = st[0], supp = st[1];
                if (tid < 32) {
                    if (tid < kept)      { kb0 = keptBox[tid];      ka0 = keptArea[tid]; }
                    if (tid + 32 < kept) { kb1 = keptBox[tid + 32]; ka1 = keptArea[tid + 32]; }
                }
                __syncthreads();
                for (int c0 = NC; c0 < NSEL; c0 += 512) {
                    const int cnt = min(512, NSEL - c0);
                    for (int t = tid; t < cnt; t += 256) {
                        u64 e = __ldcg(&g_sorted[c0 + t]);
                        int oi = (int)(u32)(e & 0xffffffffu);
                        cord[t] = oi;
                        cbx[t] = boxes4[oi];
                    }
                    __syncthreads();
                    if (tid < 32) {
                        #pragma unroll 1
                        for (int ii = 0; ii < cnt; ++ii) {
                            float4 c = cbx[ii];
                            float ca = (c.z - c.x) * (c.w - c.y);
                            bool sup = false;
                            if (tid < kept)      sup  = iou_gt(kb0, ka0, c, ca);
                            if (tid + 32 < kept) sup |= iou_gt(kb1, ka1, c, ca);
                            unsigned m = __ballot_sync(FULL, sup);
                            if (m == 0) {
                                int slot = kept;
                                if (slot < 32) { if (tid == slot)      { kb0 = c; ka0 = ca; } }
                                else           { if (tid == slot - 32) { kb1 = c; ka1 = ca; } }
                                if (tid == 0) s_sel[slot] = cord[ii];
                                kept++;
                                if (kept == 64) break;
                            } else if (supp < 64) {
                                if (tid == 0) s_supp[supp] = cord[ii];
                                supp++;
                            }
                        }
                        if (tid == 0) { st[0] = kept; st[1] = supp; }
                    }
                    __syncthreads();
                    if (st[0] >= 64) break;
                    __syncthreads();
                }
            }
            __syncthreads();

            const int keptF = st[0];
            if (tid < 64) {
                int oi = (tid < keptF) ? s_sel[tid] : s_supp[tid - keptF];
                g_sel[tid] = oi;
                if (9600 + tid < out_size) d_out[9600 + tid] = (float)labels[oi];
                if (9664 + tid < out_size) d_out[9664 + tid] = scores[oi];
            }
            __threadfence();
            __syncthreads();
            if (tid == 0) atomicExch(&g_nmsdone, 1);
        } else {
            flagwait(&g_nmsdone, tid);
        }
        if (vb == 0) { __syncthreads(); }

        // S5: cooperative gather + tails (32 blocks), then raise g_xready
        {
            // features: 32768 float4 -> 1024 per block
            for (int i = 0; i < 4; ++i) {
                int fi = vb * 1024 + i * 256 + tid;
                int r = fi >> 9, c = fi & 511;
                int oi = __ldcg(&g_sel[r]);
                ((float4*)(g_x + r * D_IN))[c] =
                    ((const float4*)(features + (size_t)oi * 2048))[c];
            }
            // embed: 12800 -> 400 per block
            for (int i = 0; i < 2; ++i) {
                int e = vb * 400 + i * 256 + tid;
                if (e < (vb + 1) * 400 && i * 256 + tid < 400) {
                    int r = e / 200, c = e - r * 200;
                    int lab = labels[__ldcg(&g_sel[r])] - 1;
                    g_x[r * D_IN + 2048 + c] = embed_w[lab * 200 + c];
                }
            }
            // pos: 8192 -> 256 per block
            {
                int p = vb * 256 + tid;
                int r = p >> 7, c = p & 127;
                int oi = __ldcg(&g_sel[r]);
                float x1 = boxes[oi * 4 + 0], y1 = boxes[oi * 4 + 1];
                float x2 = boxes[oi * 4 + 2], y2 = boxes[oi * 4 + 3];
                float w = x2 - x1 + 1.f, h = y2 - y1 + 1.f;
                float cs[4] = { x1 + 0.5f * w, y1 + 0.5f * h, w, h };
                float acc = pos_b[c];
                #pragma unroll
                for (int i = 0; i < 4; ++i) {
                    float v = (cs[i] - bn_pos[8 + i]) * rsqrtf(bn_pos[12 + i] + 1e-5f)
                              * bn_pos[i] + bn_pos[4 + i];
                    acc += v * pos_w[i * 128 + c];
                }
                g_x[r * D_IN + 2248 + c] = fmaxf(acc, 0.f);
            }
        }
        __threadfence();
        __syncthreads();
        if (tid == 0) {
            int o = atomicAdd(&g_gcnt, 1);
            if (o == 31) atomicExch(&g_xready, 1);
        }
    } else {
        // ===================== PREFETCH TEAM =====================
        prefetch_stripe(lin1_w, (D_IN * H) / 4, vb - 32, 224, tid);
        prefetch_stripe(lin2_w, (H * H) / 4, vb - 32, 224, tid);
        prefetch_stripe(lin3_w, (H * H) / 4, vb - 32, 224, tid);
        prefetch_stripe(lin4_w, (H * NCLS) / 4, vb - 32, 224, tid);
        if (vb < 64) {
            // re-zero selection scratch after it's consumed
            flagwait(&g_nmsdone, tid);
            for (int t = (vb - 32) * 128 + tid; t < 4096; t += 32 * 128)
                g_bins[t] = 0;
            if (vb == 32 && tid == 0) g_ccnt = 0;
        }
    }

    // all blocks: wait for x ready
    flagwait(&g_xready, tid);

    // ===================== MLP CHAIN (7 full barriers) =====================
    float (*As)[64][20] = (float(*)[64][20])smraw;
    float (*Ws)[16][68] = (float(*)[16][68])(smraw + 20480);
    int tgt = G;

    gemm_phase<1>(g_x, D_IN, lin1_w, H, vb & 15, vb >> 4, 152, D_IN, 16, tid, As, Ws);
    gsync(tgt, tid); tgt += G;
    reduce_h(lin1_b, bn1, g_h1, vb, tid);
    gsync(tgt, tid); tgt += G;

    gemm_phase<1>(g_h1, H, lin2_w, H, vb & 15, vb >> 4, 64, H, 16, tid, As, Ws);
    gsync(tgt, tid); tgt += G;
    reduce_h(lin2_b, bn2, g_h2, vb, tid);
    gsync(tgt, tid); tgt += G;

    gemm_phase<1>(g_h2, H, lin3_w, H, vb & 15, vb >> 4, 64, H, 16, tid, As, Ws);
    gsync(tgt, tid); tgt += G;
    reduce_h(lin3_b, bn3, g_h1, vb, tid);
    gsync(tgt, tid); tgt += G;

    if (vb < 48)
        gemm_phase<0>(g_h1, H, lin4_w, NCLS, vb % 3, vb / 3, 64, H, 3, tid, As, Ws);
    gsync(tgt, tid); tgt += G;

    {
        int idx = vb * 256 + tid;
        if (idx < 9600) {
            int r = idx / 150, col = idx - r * 150;
            int cb = col >> 6, c = col & 63;
            float s = 0.f;
            #pragma unroll
            for (int si = 0; si < 16; ++si)
                s += __ldcg(&g_part[(size_t)(si * 3 + cb) * 4096 + r * 64 + c]);
            d_out[idx] = s + lin4_b[col];
        }
    }

    // exit: last block resets all sync state for next launch / replay
    __syncthreads();
    if (tid == 0) {
        __threadfence();
        int old = atomicAdd(&g_exit, 1);
        if (old == G - 1) {
            g_bar = 0;
            g_selbar = 0;
            g_nmsdone = 0;
            g_gcnt = 0;
            g_xready = 0;
            g_exit = 0;
            __threadfence();
        }
    }
}

// ============================================================
extern "C" void kernel_launch(void* const* d_in, const int* in_sizes, int n_in,
                              void* d_out_v, int out_size)
{
    const float* boxes    = (const float*)d_in[0];
    const float* scores   = (const float*)d_in[1];
    const int*   labels   = (const int*)  d_in[2];
    const float* features = (const float*)d_in[3];
    const float* embed_w  = (const float*)d_in[4];
    const float* bn_pos   = (const float*)d_in[5];
    const float* pos_w    = (const float*)d_in[6];
    const float* pos_b    = (const float*)d_in[7];
    const float* lin1_w   = (const float*)d_in[8];
    const float* lin1_b   = (const float*)d_in[9];
    const float* bn1      = (const float*)d_in[10];
    const float* lin2_w   = (const float*)d_in[11];
    const float* lin2_b   = (const float*)d_in[12];
    const float* bn2      = (const float*)d_in[13];
    const float* lin3_w   = (const float*)d_in[14];
    const float* lin3_b   = (const float*)d_in[15];
    const float* bn3      = (const float*)d_in[16];
    const float* lin4_w   = (const float*)d_in[17];
    const float* lin4_b   = (const float*)d_in[18];
    float* d_out = (float*)d_out_v;

    fused_kernel<<<G, 256>>>(boxes, scores, labels, features, embed_w,
                             bn_pos, pos_w, pos_b,
                             lin1_w, lin1_b, bn1,
                             lin2_w, lin2_b, bn2,
                             lin3_w, lin3_b, bn3,
                             lin4_w, lin4_b, d_out, out_size);
}